// round 1
// baseline (speedup 1.0000x reference)
#include <cuda_runtime.h>
#include <math.h>

#define NB 256
#define ZD 1024
#define HD 2048
#define NT 128

#define BK 16
#define BM 64
#define BN 64
#define NKT 64          // k-tiles per launch (K-slab = 1024)
#define ASTR 132        // duplicated-A row stride in floats (2*BM + 4 pad, keeps 16B align)
#define BSTR 68         // B row stride in floats (BN + 4 pad, keeps 16B align)

// Scratch (device globals: no allocation allowed in kernel_launch)
__device__ float g_z[NB * ZD];
__device__ float g_h[NB * HD];
__device__ float g_dzp[2][NB * ZD];

// --------------------------------------------------------------------------
// Packed fp32x2 FMA (Blackwell FFMA2 — full-rate fp32 path; plain 3-reg FFMA
// is half rate on sm_103a).
__device__ __forceinline__ unsigned long long ffma2(unsigned long long a,
                                                    unsigned long long b,
                                                    unsigned long long c) {
    unsigned long long d;
    asm("fma.rn.f32x2 %0, %1, %2, %3;" : "=l"(d) : "l"(a), "l"(b), "l"(c));
    return d;
}

__device__ __forceinline__ void lds_2xu64(unsigned long long &x,
                                          unsigned long long &y, unsigned addr) {
    asm volatile("ld.shared.v2.u64 {%0, %1}, [%2];"
                 : "=l"(x), "=l"(y) : "r"(addr));
}

__device__ __forceinline__ float2 u2f2(unsigned long long v) {
    return make_float2(__uint_as_float((unsigned)v),
                       __uint_as_float((unsigned)(v >> 32)));
}

// --------------------------------------------------------------------------
// MODE 0: A = g_z (LDA=ZD), W = W1; epilogue: g_h = tanh(acc + t*wt + b1)
// MODE 1: A = g_h (LDA=HD), W = W2; split-K over blockIdx.z (kOff = z*1024);
//         epilogue: raw partial -> g_dzp[blockIdx.z]
// Both launches do a 1024-long K slab: NKT = 64 tiles of BK=16.
template <int LDA, int MODE>
__global__ void __launch_bounds__(128)
gemm_kernel(const float *__restrict__ W, const float *__restrict__ wt,
            const float *__restrict__ b1, const float *__restrict__ ts,
            int step) {
    __shared__ __align__(16) float As[2][BK][ASTR];  // duplicated pairs: As[k][2m]=As[k][2m+1]=A[m][k]
    __shared__ __align__(16) float Bs[2][BK][BSTR];

    const float *Ap = (MODE == 0) ? g_z : g_h;
    const int kOff = (MODE == 1) ? (int)blockIdx.z * 1024 : 0;

    const int tid = threadIdx.x;
    const int m0 = blockIdx.y * BM;
    const int n0 = blockIdx.x * BN;
    const int tn0 = (tid & 15) * 4;   // 4 n-columns  (2 packed pairs)
    const int tm0 = (tid >> 4) * 8;   // 8 m-rows

    const int lm = tid >> 2;          // 0..31 (loader row)
    const int lk = (tid & 3) * 4;     // 0,4,8,12 (loader k base)

    const float4 *aG0 = (const float4 *)(Ap + (size_t)(m0 + lm) * LDA + kOff + lk);
    const float4 *aG1 = (const float4 *)(Ap + (size_t)(m0 + lm + 32) * LDA + kOff + lk);
    const float4 *bG0 = (const float4 *)(W + (size_t)(n0 + lm) * LDA + kOff + lk);
    const float4 *bG1 = (const float4 *)(W + (size_t)(n0 + lm + 32) * LDA + kOff + lk);

    const unsigned sA = (unsigned)__cvta_generic_to_shared(&As[0][0][0]);
    const unsigned sB = (unsigned)__cvta_generic_to_shared(&Bs[0][0][0]);
    const unsigned aRd = sA + (unsigned)(2 * tm0) * 4u;
    const unsigned bRd = sB + (unsigned)tn0 * 4u;

    unsigned long long acc[8][2];
#pragma unroll
    for (int i = 0; i < 8; i++) { acc[i][0] = 0ull; acc[i][1] = 0ull; }

    float4 a0v = *aG0; aG0 += 4;
    float4 a1v = *aG1; aG1 += 4;
    float4 b0v = *bG0; bG0 += 4;
    float4 b1v = *bG1; bG1 += 4;

#define STORE_TILES(buf)                                                        \
    do {                                                                        \
        *(float2 *)&As[buf][lk + 0][2 * lm] = make_float2(a0v.x, a0v.x);        \
        *(float2 *)&As[buf][lk + 1][2 * lm] = make_float2(a0v.y, a0v.y);        \
        *(float2 *)&As[buf][lk + 2][2 * lm] = make_float2(a0v.z, a0v.z);        \
        *(float2 *)&As[buf][lk + 3][2 * lm] = make_float2(a0v.w, a0v.w);        \
        *(float2 *)&As[buf][lk + 0][2 * (lm + 32)] = make_float2(a1v.x, a1v.x); \
        *(float2 *)&As[buf][lk + 1][2 * (lm + 32)] = make_float2(a1v.y, a1v.y); \
        *(float2 *)&As[buf][lk + 2][2 * (lm + 32)] = make_float2(a1v.z, a1v.z); \
        *(float2 *)&As[buf][lk + 3][2 * (lm + 32)] = make_float2(a1v.w, a1v.w); \
        Bs[buf][lk + 0][lm] = b0v.x;                                            \
        Bs[buf][lk + 1][lm] = b0v.y;                                            \
        Bs[buf][lk + 2][lm] = b0v.z;                                            \
        Bs[buf][lk + 3][lm] = b0v.w;                                            \
        Bs[buf][lk + 0][lm + 32] = b1v.x;                                       \
        Bs[buf][lk + 1][lm + 32] = b1v.y;                                       \
        Bs[buf][lk + 2][lm + 32] = b1v.z;                                       \
        Bs[buf][lk + 3][lm + 32] = b1v.w;                                       \
    } while (0)

    STORE_TILES(0);
    __syncthreads();

    int cur = 0;
    for (int kt = 0; kt < NKT; ++kt) {
        if (kt + 1 < NKT) {
            a0v = *aG0; aG0 += 4;
            a1v = *aG1; aG1 += 4;
            b0v = *bG0; bG0 += 4;
            b1v = *bG1; bG1 += 4;
        }
        const unsigned aB = aRd + (unsigned)cur * (BK * ASTR * 4);
        const unsigned bB = bRd + (unsigned)cur * (BK * BSTR * 4);
#pragma unroll
        for (int kk = 0; kk < BK; ++kk) {
            unsigned long long a[8], bb0, bb1;
            lds_2xu64(a[0], a[1], aB + kk * (ASTR * 4) + 0);
            lds_2xu64(a[2], a[3], aB + kk * (ASTR * 4) + 16);
            lds_2xu64(a[4], a[5], aB + kk * (ASTR * 4) + 32);
            lds_2xu64(a[6], a[7], aB + kk * (ASTR * 4) + 48);
            lds_2xu64(bb0, bb1, bB + kk * (BSTR * 4));
#pragma unroll
            for (int i = 0; i < 8; i++) {
                acc[i][0] = ffma2(a[i], bb0, acc[i][0]);
                acc[i][1] = ffma2(a[i], bb1, acc[i][1]);
            }
        }
        if (kt + 1 < NKT) STORE_TILES(1 - cur);
        __syncthreads();
        cur ^= 1;
    }
#undef STORE_TILES

    if (MODE == 0) {
        const float t = ts[step];
        const int n = n0 + tn0;
        const float c0 = fmaf(t, wt[n + 0], b1[n + 0]);
        const float c1 = fmaf(t, wt[n + 1], b1[n + 1]);
        const float c2 = fmaf(t, wt[n + 2], b1[n + 2]);
        const float c3 = fmaf(t, wt[n + 3], b1[n + 3]);
#pragma unroll
        for (int i = 0; i < 8; i++) {
            float2 p0 = u2f2(acc[i][0]);
            float2 p1 = u2f2(acc[i][1]);
            float4 r = make_float4(tanhf(p0.x + c0), tanhf(p0.y + c1),
                                   tanhf(p1.x + c2), tanhf(p1.y + c3));
            *(float4 *)&g_h[(size_t)(m0 + tm0 + i) * HD + n] = r;
        }
    } else {
        float *dst = g_dzp[blockIdx.z];
        const int n = n0 + tn0;
#pragma unroll
        for (int i = 0; i < 8; i++) {
            float2 p0 = u2f2(acc[i][0]);
            float2 p1 = u2f2(acc[i][1]);
            *(float4 *)&dst[(size_t)(m0 + tm0 + i) * ZD + n] =
                make_float4(p0.x, p0.y, p1.x, p1.y);
        }
    }
}

// --------------------------------------------------------------------------
// Euler update: z += dt * (dzp0 + dzp1 + b2); also scatter into trajectory.
__global__ void __launch_bounds__(256)
euler_kernel(const float *__restrict__ b2, const float *__restrict__ ts,
             float *__restrict__ out, int step) {
    const int idx = blockIdx.x * blockDim.x + threadIdx.x;  // < NB*ZD
    const float dt = ts[step + 1] - ts[step];
    const int n = idx & (ZD - 1);
    const int m = idx >> 10;
    const float dz = g_dzp[0][idx] + g_dzp[1][idx] + b2[n];
    const float zn = g_z[idx] + dt * dz;
    g_z[idx] = zn;
    out[(size_t)m * (ZD * NT) + (size_t)n * NT + (step + 1)] = zn;
}

// z init + trajectory slice t=0
__global__ void __launch_bounds__(256)
init_kernel(const float *__restrict__ z0, float *__restrict__ out) {
    const int idx = blockIdx.x * blockDim.x + threadIdx.x;  // < NB*ZD
    const float v = z0[idx];
    g_z[idx] = v;
    const int n = idx & (ZD - 1);
    const int m = idx >> 10;
    out[(size_t)m * (ZD * NT) + (size_t)n * NT] = v;
}

// --------------------------------------------------------------------------
extern "C" void kernel_launch(void *const *d_in, const int *in_sizes, int n_in,
                              void *d_out, int out_size) {
    const float *z0 = (const float *)d_in[0];
    const float *ts = (const float *)d_in[1];
    const float *W1 = (const float *)d_in[2];
    const float *wt = (const float *)d_in[3];
    const float *b1 = (const float *)d_in[4];
    const float *W2 = (const float *)d_in[5];
    const float *b2 = (const float *)d_in[6];
    float *out = (float *)d_out;

    init_kernel<<<(NB * ZD) / 256, 256>>>(z0, out);

    for (int s = 0; s < NT - 1; ++s) {
        // h = tanh(z @ W1^T + ts[s]*wt + b1)       [256 x 2048]
        gemm_kernel<ZD, 0><<<dim3(HD / BN, NB / BM, 1), 128>>>(W1, wt, b1, ts, s);
        // dz partials = h @ W2^T (split-K = 2)     [2][256 x 1024]
        gemm_kernel<HD, 1><<<dim3(ZD / BN, NB / BM, 2), 128>>>(W2, wt, b1, ts, s);
        // z += dt*(dz + b2); write trajectory slice s+1
        euler_kernel<<<(NB * ZD) / 256, 256>>>(b2, ts, out, s);
    }
}

// round 4
// speedup vs baseline: 1.2575x; 1.2575x over previous
#include <cuda_runtime.h>
#include <math.h>

#define NB 256
#define ZD 1024
#define HD 2048
#define NT 128
#define NP (NB * ZD)     // 262144 elements per time slice

#define BK 16
#define BM 64
#define BN 64
#define NKT 64           // k-tiles per launch (K-slab = 1024)
#define ASTR 132         // duplicated-A row stride in floats (2*BM + 4)
#define BSTR 68          // B row stride in floats (BN + 4)

// Scratch (device globals: allocation is banned in kernel_launch)
__device__ float g_z[NP];
__device__ float g_h[NB * HD];
__device__ float g_dzp[2][NP];
__device__ float g_traj[NT * NP];   // [t][m*ZD+n], 128 MB

// --------------------------------------------------------------------------
// Packed fp32x2 FMA (full-rate fp32 on sm_103a; 3-reg FFMA is half rate).
__device__ __forceinline__ unsigned long long ffma2(unsigned long long a,
                                                    unsigned long long b,
                                                    unsigned long long c) {
    unsigned long long d;
    asm("fma.rn.f32x2 %0, %1, %2, %3;" : "=l"(d) : "l"(a), "l"(b), "l"(c));
    return d;
}

__device__ __forceinline__ void lds_2xu64(unsigned long long &x,
                                          unsigned long long &y, unsigned addr) {
    asm volatile("ld.shared.v2.u64 {%0, %1}, [%2];"
                 : "=l"(x), "=l"(y) : "r"(addr));
}

__device__ __forceinline__ float2 u2f2(unsigned long long v) {
    return make_float2(__uint_as_float((unsigned)v),
                       __uint_as_float((unsigned)(v >> 32)));
}

// --------------------------------------------------------------------------
// 256 threads, 64x64 tile, 4x4 micro-tile, double-buffered smem, FFMA2 core.
// MODE 0: A = g_z (LDA=ZD), W = W1; epilogue: g_h = tanh(acc + t*wt + b1)
// MODE 1: A = g_h (LDA=HD), W = W2; split-K via blockIdx.z (kOff = z*1024);
//         epilogue: raw partial -> g_dzp[blockIdx.z]
template <int LDA, int MODE>
__global__ void __launch_bounds__(256)
gemm_kernel(const float *__restrict__ W, const float *__restrict__ wt,
            const float *__restrict__ b1, const float *__restrict__ ts,
            int step) {
    __shared__ __align__(16) float As[2][BK][ASTR]; // As[k][2m]=As[k][2m+1]=A[m][k]
    __shared__ __align__(16) float Bs[2][BK][BSTR];

    const float *Ap = (MODE == 0) ? g_z : g_h;
    const int kOff = (MODE == 1) ? (int)blockIdx.z * 1024 : 0;

    const int tid = threadIdx.x;
    const int m0 = blockIdx.y * BM;
    const int n0 = blockIdx.x * BN;
    const int tn0 = (tid & 15) * 4;  // 4 n-columns (2 packed pairs)
    const int tm0 = (tid >> 4) * 4;  // 4 m-rows

    const int lr = tid >> 2;         // 0..63 loader row
    const int lk = (tid & 3) * 4;    // 0,4,8,12 loader k base

    const float4 *aG = (const float4 *)(Ap + (size_t)(m0 + lr) * LDA + kOff + lk);
    const float4 *bG = (const float4 *)(W + (size_t)(n0 + lr) * LDA + kOff + lk);

    const unsigned sA = (unsigned)__cvta_generic_to_shared(&As[0][0][0]);
    const unsigned sB = (unsigned)__cvta_generic_to_shared(&Bs[0][0][0]);
    const unsigned aRd = sA + (unsigned)(2 * tm0) * 4u;
    const unsigned bRd = sB + (unsigned)tn0 * 4u;

    unsigned long long acc[4][2];
#pragma unroll
    for (int i = 0; i < 4; i++) { acc[i][0] = 0ull; acc[i][1] = 0ull; }

    float4 av = *aG; aG += 4;   // +16 floats = next k-tile
    float4 bv = *bG; bG += 4;

#define STORE_TILES(buf)                                                  \
    do {                                                                  \
        *(float2 *)&As[buf][lk + 0][2 * lr] = make_float2(av.x, av.x);    \
        *(float2 *)&As[buf][lk + 1][2 * lr] = make_float2(av.y, av.y);    \
        *(float2 *)&As[buf][lk + 2][2 * lr] = make_float2(av.z, av.z);    \
        *(float2 *)&As[buf][lk + 3][2 * lr] = make_float2(av.w, av.w);    \
        Bs[buf][lk + 0][lr] = bv.x;                                       \
        Bs[buf][lk + 1][lr] = bv.y;                                       \
        Bs[buf][lk + 2][lr] = bv.z;                                       \
        Bs[buf][lk + 3][lr] = bv.w;                                       \
    } while (0)

    STORE_TILES(0);
    __syncthreads();

    int cur = 0;
    for (int kt = 0; kt < NKT; ++kt) {
        if (kt + 1 < NKT) {
            av = *aG; aG += 4;
            bv = *bG; bG += 4;
        }
        const unsigned aB = aRd + (unsigned)cur * (BK * ASTR * 4);
        const unsigned bB = bRd + (unsigned)cur * (BK * BSTR * 4);
#pragma unroll
        for (int kk = 0; kk < BK; ++kk) {
            unsigned long long a[4], bb0, bb1;
            lds_2xu64(a[0], a[1], aB + kk * (ASTR * 4) + 0);
            lds_2xu64(a[2], a[3], aB + kk * (ASTR * 4) + 16);
            lds_2xu64(bb0, bb1, bB + kk * (BSTR * 4));
#pragma unroll
            for (int i = 0; i < 4; i++) {
                acc[i][0] = ffma2(a[i], bb0, acc[i][0]);
                acc[i][1] = ffma2(a[i], bb1, acc[i][1]);
            }
        }
        if (kt + 1 < NKT) STORE_TILES(1 - cur);
        __syncthreads();
        cur ^= 1;
    }
#undef STORE_TILES

    if (MODE == 0) {
        const float t = ts[step];
        const int n = n0 + tn0;
        const float c0 = fmaf(t, wt[n + 0], b1[n + 0]);
        const float c1 = fmaf(t, wt[n + 1], b1[n + 1]);
        const float c2 = fmaf(t, wt[n + 2], b1[n + 2]);
        const float c3 = fmaf(t, wt[n + 3], b1[n + 3]);
#pragma unroll
        for (int i = 0; i < 4; i++) {
            float2 p0 = u2f2(acc[i][0]);
            float2 p1 = u2f2(acc[i][1]);
            float4 r = make_float4(tanhf(p0.x + c0), tanhf(p0.y + c1),
                                   tanhf(p1.x + c2), tanhf(p1.y + c3));
            *(float4 *)&g_h[(size_t)(m0 + tm0 + i) * HD + n] = r;
        }
    } else {
        float *dst = g_dzp[blockIdx.z];
        const int n = n0 + tn0;
#pragma unroll
        for (int i = 0; i < 4; i++) {
            float2 p0 = u2f2(acc[i][0]);
            float2 p1 = u2f2(acc[i][1]);
            *(float4 *)&dst[(size_t)(m0 + tm0 + i) * ZD + n] =
                make_float4(p0.x, p0.y, p1.x, p1.y);
        }
    }
}

// --------------------------------------------------------------------------
// z += dt * (dzp0 + dzp1 + b2); write contiguous trajectory slice s+1.
__global__ void __launch_bounds__(256)
euler_kernel(const float *__restrict__ b2, const float *__restrict__ ts,
             int step) {
    const int idx = blockIdx.x * blockDim.x + threadIdx.x;  // < NP
    const float dt = ts[step + 1] - ts[step];
    const int n = idx & (ZD - 1);
    const float dz = g_dzp[0][idx] + g_dzp[1][idx] + b2[n];
    const float zn = g_z[idx] + dt * dz;
    g_z[idx] = zn;
    g_traj[(size_t)(step + 1) * NP + idx] = zn;
}

__global__ void __launch_bounds__(256)
init_kernel(const float *__restrict__ z0) {
    const int idx = blockIdx.x * blockDim.x + threadIdx.x;  // < NP
    const float v = z0[idx];
    g_z[idx] = v;
    g_traj[idx] = v;
}

// --------------------------------------------------------------------------
// Final transpose: out[p*NT + t] = g_traj[t*NP + p],  p = m*ZD+n.
// 32(t) x 32(p) tiles via smem; both read and write fully coalesced.
__global__ void __launch_bounds__(256)
transpose_kernel(float *__restrict__ out) {
    __shared__ float sm[32][33];
    const int p0 = blockIdx.x * 32;
    const int t0 = blockIdx.y * 32;
    const int tx = threadIdx.x;       // 0..31
    const int ty = threadIdx.y;       // 0..7
#pragma unroll
    for (int i = 0; i < 4; i++) {
        const int tl = ty + 8 * i;
        sm[tl][tx] = g_traj[(size_t)(t0 + tl) * NP + p0 + tx];
    }
    __syncthreads();
#pragma unroll
    for (int i = 0; i < 4; i++) {
        const int pl = ty + 8 * i;
        out[(size_t)(p0 + pl) * NT + t0 + tx] = sm[tx][pl];
    }
}

// --------------------------------------------------------------------------
extern "C" void kernel_launch(void *const *d_in, const int *in_sizes, int n_in,
                              void *d_out, int out_size) {
    const float *z0 = (const float *)d_in[0];
    const float *ts = (const float *)d_in[1];
    const float *W1 = (const float *)d_in[2];
    const float *wt = (const float *)d_in[3];
    const float *b1 = (const float *)d_in[4];
    const float *W2 = (const float *)d_in[5];
    const float *b2 = (const float *)d_in[6];
    float *out = (float *)d_out;

    init_kernel<<<NP / 256, 256>>>(z0);

    for (int s = 0; s < NT - 1; ++s) {
        // h = tanh(z @ W1^T + ts[s]*wt + b1)         [256 x 2048]
        gemm_kernel<ZD, 0><<<dim3(HD / BN, NB / BM, 1), 256>>>(W1, wt, b1, ts, s);
        // dz partials = h @ W2^T (split-K = 2)       [2][256 x 1024]
        gemm_kernel<HD, 1><<<dim3(ZD / BN, NB / BM, 2), 256>>>(W2, wt, b1, ts, s);
        // z += dt*(dz + b2); contiguous trajectory slice s+1
        euler_kernel<<<NP / 256, 256>>>(b2, ts, s);
    }

    // [T][B*Z] -> [B*Z][T]
    transpose_kernel<<<dim3(NP / 32, NT / 32), dim3(32, 8)>>>(out);
}

// round 6
// speedup vs baseline: 2.6865x; 2.1364x over previous
#include <cuda_runtime.h>
#include <cuda_bf16.h>
#include <math.h>
#include <stdint.h>

#define NB 256
#define ZD 1024
#define HD 2048
#define NT 128
#define NP (NB * ZD)

#define KCH 32            // k elements per chunk
#define NCHUNK 32         // 1024 / 32
#define SROW 80           // padded row stride bytes (64B data + 16B pad)
#define A_SPLIT 5120      // 64 rows * 80B  (hi block size)
#define B_BASE 10240      // A hi + A lo
#define STAGE_BYTES 20480 // Ahi+Alo+Bhi+Blo
// 2 stages: 40960 B static shared (< 48K default)

// ---------------- device scratch ------------------------------------------
__device__ float g_z[NP];
__device__ float g_dzp[2][NP];
__device__ float g_traj[NT * NP];
__device__ __nv_bfloat16 g_zhi[NP], g_zlo[NP];
__device__ __nv_bfloat16 g_hhi[NB * HD], g_hlo[NB * HD];
__device__ __nv_bfloat16 g_W1hi[HD * ZD], g_W1lo[HD * ZD];
__device__ __nv_bfloat16 g_W2hi[ZD * HD], g_W2lo[ZD * HD];

// ---------------- PTX helpers ---------------------------------------------
__device__ __forceinline__ void cp16(uint32_t dst, const void *src) {
    asm volatile("cp.async.cg.shared.global [%0], [%1], 16;" :: "r"(dst), "l"(src));
}
__device__ __forceinline__ void cp_commit() {
    asm volatile("cp.async.commit_group;" ::: "memory");
}
template <int N>
__device__ __forceinline__ void cp_wait() {
    asm volatile("cp.async.wait_group %0;" :: "n"(N) : "memory");
}

__device__ __forceinline__ void ldsm4(uint32_t &r0, uint32_t &r1, uint32_t &r2,
                                      uint32_t &r3, uint32_t a) {
    asm volatile("ldmatrix.sync.aligned.m8n8.x4.shared.b16 {%0,%1,%2,%3}, [%4];"
                 : "=r"(r0), "=r"(r1), "=r"(r2), "=r"(r3) : "r"(a));
}

__device__ __forceinline__ void mma16816(float *c, const uint32_t *a,
                                         const uint32_t *b) {
    asm volatile(
        "mma.sync.aligned.m16n8k16.row.col.f32.bf16.bf16.f32 "
        "{%0,%1,%2,%3}, {%4,%5,%6,%7}, {%8,%9}, {%0,%1,%2,%3};"
        : "+f"(c[0]), "+f"(c[1]), "+f"(c[2]), "+f"(c[3])
        : "r"(a[0]), "r"(a[1]), "r"(a[2]), "r"(a[3]), "r"(b[0]), "r"(b[1]));
}

__device__ __forceinline__ void bf16_split(float v, __nv_bfloat16 &hi,
                                           __nv_bfloat16 &lo) {
    hi = __float2bfloat16_rn(v);
    lo = __float2bfloat16_rn(v - __bfloat162float(hi));
}
__device__ __forceinline__ uint32_t pack2(__nv_bfloat16 a, __nv_bfloat16 b) {
    return (uint32_t)__bfloat16_as_ushort(a) |
           ((uint32_t)__bfloat16_as_ushort(b) << 16);
}

// ---------------- warp-MMA GEMM -------------------------------------------
// D[m,n] = sum_k A[m,k]*B[n,k] via 3 bf16 products (hi*hi + hi*lo + lo*hi).
// MODE 0: A = z splits, B = W1 splits; epilogue tanh(acc + t*wt + b1) -> h splits
// MODE 1: A = h splits, B = W2 splits; split-K over blockIdx.z -> g_dzp[z]
template <int LDA, int MODE>
__global__ void __launch_bounds__(128)
gemm_mma(const float *__restrict__ wt, const float *__restrict__ b1,
         const float *__restrict__ ts, int step) {
    __shared__ __align__(128) char smem[2 * STAGE_BYTES];
    const uint32_t s0 = (uint32_t)__cvta_generic_to_shared(smem);

    const int tid = threadIdx.x;
    const int wid = tid >> 5, l = tid & 31;
    const int wm = wid & 1, wn = wid >> 1;       // warp grid 2(m) x 2(n)
    const int g = l >> 2, tig = l & 3;

    const int m0 = blockIdx.y * 64, n0 = blockIdx.x * 64;
    const int kOff = (MODE == 1) ? (int)blockIdx.z * 1024 : 0;

    const __nv_bfloat16 *Ahi = MODE ? g_hhi : g_zhi;
    const __nv_bfloat16 *Alo = MODE ? g_hlo : g_zlo;
    const __nv_bfloat16 *Bhi = MODE ? g_W2hi : g_W1hi;
    const __nv_bfloat16 *Blo = MODE ? g_W2lo : g_W1lo;

    // loader mapping: 128 threads -> 64 rows x 2 halves (32B each)
    const int row = tid >> 1;
    const int half = tid & 1;
    const __nv_bfloat16 *Ah = Ahi + (size_t)(m0 + row) * LDA + kOff;
    const __nv_bfloat16 *Al = Alo + (size_t)(m0 + row) * LDA + kOff;
    const __nv_bfloat16 *Bh = Bhi + (size_t)(n0 + row) * LDA + kOff;
    const __nv_bfloat16 *Bl = Blo + (size_t)(n0 + row) * LDA + kOff;
    const uint32_t dBase = s0 + (uint32_t)row * SROW + (uint32_t)half * 32;

    // ldmatrix per-lane addresses (within a stage)
    // A tile (16x16, row-major, k-contig): lanes 0-15 rows, lanes 16-31 k+8
    const uint32_t aOff = (uint32_t)(wm * 32 + (l & 15)) * SROW + (uint32_t)(l >> 4) * 16;
    // B tile (n16 x k16, n rows): m0:(n0-7,k0-7) m1:(n0-7,k8-15) m2:(n8-15,k0-7) m3:(n8-15,k8-15)
    const uint32_t bOff = (uint32_t)(wn * 32 + ((l >> 4) << 3) + (l & 7)) * SROW +
                          (uint32_t)((l >> 3) & 1) * 16;

    float acc[2][4][4];
#pragma unroll
    for (int mt = 0; mt < 2; mt++)
#pragma unroll
        for (int nt = 0; nt < 4; nt++)
#pragma unroll
            for (int i = 0; i < 4; i++) acc[mt][nt][i] = 0.0f;

    auto load = [&](int c, int st) {
        const uint32_t d = dBase + (uint32_t)st * STAGE_BYTES;
        const int e = c * KCH + half * 16;
        cp16(d, Ah + e);                 cp16(d + 16, Ah + e + 8);
        cp16(d + A_SPLIT, Al + e);       cp16(d + A_SPLIT + 16, Al + e + 8);
        cp16(d + B_BASE, Bh + e);        cp16(d + B_BASE + 16, Bh + e + 8);
        cp16(d + B_BASE + A_SPLIT, Bl + e);
        cp16(d + B_BASE + A_SPLIT + 16, Bl + e + 8);
        cp_commit();
    };

    load(0, 0);
    load(1, 1);

#pragma unroll 1
    for (int c = 0; c < NCHUNK; c++) {
        const int st = c & 1;
        if (c < NCHUNK - 1) cp_wait<1>(); else cp_wait<0>();
        __syncthreads();

        const uint32_t sb = s0 + (uint32_t)st * STAGE_BYTES;
#pragma unroll
        for (int kk = 0; kk < 2; kk++) {
            uint32_t aF[2][2][4], bF[2][2][4];
#pragma unroll
            for (int sp = 0; sp < 2; sp++) {
#pragma unroll
                for (int mt = 0; mt < 2; mt++)
                    ldsm4(aF[sp][mt][0], aF[sp][mt][1], aF[sp][mt][2], aF[sp][mt][3],
                          sb + sp * A_SPLIT + aOff + mt * (16 * SROW) + kk * 32);
#pragma unroll
                for (int np = 0; np < 2; np++)
                    ldsm4(bF[sp][np][0], bF[sp][np][1], bF[sp][np][2], bF[sp][np][3],
                          sb + B_BASE + sp * A_SPLIT + bOff + np * (16 * SROW) + kk * 32);
            }
#pragma unroll
            for (int mt = 0; mt < 2; mt++)
#pragma unroll
                for (int nt = 0; nt < 4; nt++) {
                    const uint32_t *bh = &bF[0][nt >> 1][(nt & 1) * 2];
                    const uint32_t *bl = &bF[1][nt >> 1][(nt & 1) * 2];
                    mma16816(acc[mt][nt], aF[0][mt], bh);   // hi*hi
                    mma16816(acc[mt][nt], aF[0][mt], bl);   // hi*lo
                    mma16816(acc[mt][nt], aF[1][mt], bh);   // lo*hi
                }
        }

        if (c + 2 < NCHUNK) {
            __syncthreads();            // all warps done reading stage st
            load(c + 2, st);
        }
    }

    // ---------------- epilogue ----------------
    if (MODE == 0) {
        const float t = ts[step];
#pragma unroll
        for (int mt = 0; mt < 2; mt++) {
            const int mr = m0 + wm * 32 + mt * 16 + g;
#pragma unroll
            for (int nt = 0; nt < 4; nt++) {
                const int n = n0 + wn * 32 + nt * 8 + tig * 2;
                const float c0 = fmaf(t, wt[n], b1[n]);
                const float c1 = fmaf(t, wt[n + 1], b1[n + 1]);
                const float v0 = tanhf(acc[mt][nt][0] + c0);
                const float v1 = tanhf(acc[mt][nt][1] + c1);
                const float v2 = tanhf(acc[mt][nt][2] + c0);
                const float v3 = tanhf(acc[mt][nt][3] + c1);
                __nv_bfloat16 h0, l0, h1, l1, h2, l2, h3, l3;
                bf16_split(v0, h0, l0); bf16_split(v1, h1, l1);
                bf16_split(v2, h2, l2); bf16_split(v3, h3, l3);
                *(uint32_t *)(g_hhi + (size_t)mr * HD + n) = pack2(h0, h1);
                *(uint32_t *)(g_hlo + (size_t)mr * HD + n) = pack2(l0, l1);
                *(uint32_t *)(g_hhi + (size_t)(mr + 8) * HD + n) = pack2(h2, h3);
                *(uint32_t *)(g_hlo + (size_t)(mr + 8) * HD + n) = pack2(l2, l3);
            }
        }
    } else {
        float *dst = g_dzp[blockIdx.z];
#pragma unroll
        for (int mt = 0; mt < 2; mt++) {
            const int mr = m0 + wm * 32 + mt * 16 + g;
#pragma unroll
            for (int nt = 0; nt < 4; nt++) {
                const int n = n0 + wn * 32 + nt * 8 + tig * 2;
                *(float2 *)(dst + (size_t)mr * ZD + n) =
                    make_float2(acc[mt][nt][0], acc[mt][nt][1]);
                *(float2 *)(dst + (size_t)(mr + 8) * ZD + n) =
                    make_float2(acc[mt][nt][2], acc[mt][nt][3]);
            }
        }
    }
}

// ---------------- pointwise kernels ---------------------------------------
__global__ void __launch_bounds__(256)
euler_kernel(const float *__restrict__ b2, const float *__restrict__ ts, int step) {
    const int base = (blockIdx.x * 256 + threadIdx.x) * 4;
    const float dt = ts[step + 1] - ts[step];
    const float4 a = *(const float4 *)(g_dzp[0] + base);
    const float4 b = *(const float4 *)(g_dzp[1] + base);
    const float4 z = *(const float4 *)(g_z + base);
    const int n = base & (ZD - 1);
    const float4 bb = *(const float4 *)(b2 + n);
    float4 zn;
    zn.x = fmaf(dt, a.x + b.x + bb.x, z.x);
    zn.y = fmaf(dt, a.y + b.y + bb.y, z.y);
    zn.z = fmaf(dt, a.z + b.z + bb.z, z.z);
    zn.w = fmaf(dt, a.w + b.w + bb.w, z.w);
    *(float4 *)(g_z + base) = zn;
    *(float4 *)(g_traj + (size_t)(step + 1) * NP + base) = zn;
    __nv_bfloat16 h[4], l[4];
    bf16_split(zn.x, h[0], l[0]); bf16_split(zn.y, h[1], l[1]);
    bf16_split(zn.z, h[2], l[2]); bf16_split(zn.w, h[3], l[3]);
    *(uint2 *)(g_zhi + base) = make_uint2(pack2(h[0], h[1]), pack2(h[2], h[3]));
    *(uint2 *)(g_zlo + base) = make_uint2(pack2(l[0], l[1]), pack2(l[2], l[3]));
}

__global__ void __launch_bounds__(256)
init_kernel(const float *__restrict__ z0) {
    const int base = (blockIdx.x * 256 + threadIdx.x) * 4;
    const float4 v = *(const float4 *)(z0 + base);
    *(float4 *)(g_z + base) = v;
    *(float4 *)(g_traj + base) = v;
    __nv_bfloat16 h[4], l[4];
    bf16_split(v.x, h[0], l[0]); bf16_split(v.y, h[1], l[1]);
    bf16_split(v.z, h[2], l[2]); bf16_split(v.w, h[3], l[3]);
    *(uint2 *)(g_zhi + base) = make_uint2(pack2(h[0], h[1]), pack2(h[2], h[3]));
    *(uint2 *)(g_zlo + base) = make_uint2(pack2(l[0], l[1]), pack2(l[2], l[3]));
}

__global__ void __launch_bounds__(256)
wsplit_kernel(const float *__restrict__ src, int which) {
    const int base = (blockIdx.x * 256 + threadIdx.x) * 4;
    __nv_bfloat16 *dh = which ? g_W2hi : g_W1hi;
    __nv_bfloat16 *dl = which ? g_W2lo : g_W1lo;
    const float4 v = *(const float4 *)(src + base);
    __nv_bfloat16 h[4], l[4];
    bf16_split(v.x, h[0], l[0]); bf16_split(v.y, h[1], l[1]);
    bf16_split(v.z, h[2], l[2]); bf16_split(v.w, h[3], l[3]);
    *(uint2 *)(dh + base) = make_uint2(pack2(h[0], h[1]), pack2(h[2], h[3]));
    *(uint2 *)(dl + base) = make_uint2(pack2(l[0], l[1]), pack2(l[2], l[3]));
}

// [T][B*Z] -> [B*Z][T]
__global__ void __launch_bounds__(256)
transpose_kernel(float *__restrict__ out) {
    __shared__ float sm[32][33];
    const int p0 = blockIdx.x * 32;
    const int t0 = blockIdx.y * 32;
    const int tx = threadIdx.x;
    const int ty = threadIdx.y;
#pragma unroll
    for (int i = 0; i < 4; i++) {
        const int tl = ty + 8 * i;
        sm[tl][tx] = g_traj[(size_t)(t0 + tl) * NP + p0 + tx];
    }
    __syncthreads();
#pragma unroll
    for (int i = 0; i < 4; i++) {
        const int pl = ty + 8 * i;
        out[(size_t)(p0 + pl) * NT + t0 + tx] = sm[tx][pl];
    }
}

// ---------------------------------------------------------------------------
extern "C" void kernel_launch(void *const *d_in, const int *in_sizes, int n_in,
                              void *d_out, int out_size) {
    const float *z0 = (const float *)d_in[0];
    const float *ts = (const float *)d_in[1];
    const float *W1 = (const float *)d_in[2];
    const float *wt = (const float *)d_in[3];
    const float *b1 = (const float *)d_in[4];
    const float *W2 = (const float *)d_in[5];
    const float *b2 = (const float *)d_in[6];
    float *out = (float *)d_out;

    wsplit_kernel<<<(HD * ZD) / 1024, 256>>>(W1, 0);
    wsplit_kernel<<<(HD * ZD) / 1024, 256>>>(W2, 1);
    init_kernel<<<NP / 1024, 256>>>(z0);

    for (int s = 0; s < NT - 1; ++s) {
        // h = tanh(z @ W1^T + ts[s]*wt + b1)   [256 x 2048]
        gemm_mma<ZD, 0><<<dim3(HD / 64, NB / 64, 1), 128>>>(wt, b1, ts, s);
        // dz partials = h @ W2^T (split-K=2)   [2][256 x 1024]
        gemm_mma<HD, 1><<<dim3(ZD / 64, NB / 64, 2), 128>>>(wt, b1, ts, s);
        // z += dt*(dz + b2); trajectory slice s+1
        euler_kernel<<<NP / 1024, 256>>>(b2, ts, s);
    }

    transpose_kernel<<<dim3(NP / 32, NT / 32), dim3(32, 8)>>>(out);
}

// round 8
// speedup vs baseline: 2.9236x; 1.0883x over previous
#include <cuda_runtime.h>
#include <cuda_bf16.h>
#include <math.h>
#include <stdint.h>

#define NB 256
#define ZD 1024
#define HD 2048
#define NT 128
#define NP (NB * ZD)

#define KCH 32            // k elements per chunk
#define NCHUNK 16         // K slab = 512 per CTA (split-K)
#define A_ROWS 128
#define B_ROWS 64
#define A_SPL 8192        // 128 rows * 64B
#define B_SPL 4096        // 64 rows * 64B
#define OFF_ALO 8192
#define OFF_BHI 16384
#define OFF_BLO 20480
#define STAGE 24576       // 2 stages = 49152 B static (the 48KB cap)

// ---------------- device scratch ------------------------------------------
__device__ float g_hp[2][NB * HD];      // GEMM1 split-K partials
__device__ float g_dzp[4][NB * ZD];     // GEMM2 split-K partials
__device__ float g_z[NP];
__device__ float g_traj[NT * NP];
__device__ __nv_bfloat16 g_zhi[NP], g_zlo[NP];
__device__ __nv_bfloat16 g_hhi[NB * HD], g_hlo[NB * HD];
__device__ __nv_bfloat16 g_W1hi[HD * ZD], g_W1lo[HD * ZD];
__device__ __nv_bfloat16 g_W2hi[ZD * HD], g_W2lo[ZD * HD];

// ---------------- PTX helpers ---------------------------------------------
__device__ __forceinline__ void cp16(uint32_t dst, const void *src) {
    asm volatile("cp.async.cg.shared.global [%0], [%1], 16;" :: "r"(dst), "l"(src));
}
__device__ __forceinline__ void cp_commit() {
    asm volatile("cp.async.commit_group;" ::: "memory");
}
template <int N>
__device__ __forceinline__ void cp_wait() {
    asm volatile("cp.async.wait_group %0;" :: "n"(N) : "memory");
}
__device__ __forceinline__ void ldsm4(uint32_t &r0, uint32_t &r1, uint32_t &r2,
                                      uint32_t &r3, uint32_t a) {
    asm volatile("ldmatrix.sync.aligned.m8n8.x4.shared.b16 {%0,%1,%2,%3}, [%4];"
                 : "=r"(r0), "=r"(r1), "=r"(r2), "=r"(r3) : "r"(a));
}
__device__ __forceinline__ void mma16816(float *c, const uint32_t *a,
                                         const uint32_t *b) {
    asm volatile(
        "mma.sync.aligned.m16n8k16.row.col.f32.bf16.bf16.f32 "
        "{%0,%1,%2,%3}, {%4,%5,%6,%7}, {%8,%9}, {%0,%1,%2,%3};"
        : "+f"(c[0]), "+f"(c[1]), "+f"(c[2]), "+f"(c[3])
        : "r"(a[0]), "r"(a[1]), "r"(a[2]), "r"(a[3]), "r"(b[0]), "r"(b[1]));
}
__device__ __forceinline__ void bf16_split(float v, __nv_bfloat16 &hi,
                                           __nv_bfloat16 &lo) {
    hi = __float2bfloat16_rn(v);
    lo = __float2bfloat16_rn(v - __bfloat162float(hi));
}
__device__ __forceinline__ uint32_t pack2(__nv_bfloat16 a, __nv_bfloat16 b) {
    return (uint32_t)__bfloat16_as_ushort(a) |
           ((uint32_t)__bfloat16_as_ushort(b) << 16);
}
// swizzled byte offset inside one split region (row r, 16B-column c16)
__device__ __forceinline__ uint32_t swz(uint32_t r, uint32_t c16) {
    return r * 64u + ((c16 ^ ((r >> 1) & 3u)) << 4);
}

// ---------------- warp-MMA GEMM (128m x 64n CTA tile, 256 thr, split-K) ----
// D[m,n] = sum_k A[m,k]*B[n,k] via 3 bf16 products (hi*hi + hi*lo + lo*hi).
// MODE 0: A = z splits (LDA=1024), B = W1 splits; out -> g_hp[z] (LDO=HD)
// MODE 1: A = h splits (LDA=2048), B = W2 splits; out -> g_dzp[z] (LDO=ZD)
template <int LDA, int MODE>
__global__ void __launch_bounds__(256)
gemm_mma() {
    __shared__ __align__(128) char smem[2 * STAGE];
    const uint32_t s0 = (uint32_t)__cvta_generic_to_shared(smem);

    const int tid = threadIdx.x;
    const int wid = tid >> 5, l = tid & 31;
    const int wm = wid & 3, wn = wid >> 2;        // warp grid 4(m) x 2(n)
    const int g = l >> 2, tig = l & 3;

    const int m0 = blockIdx.y * 128, n0 = blockIdx.x * 64;
    const int kOff = (int)blockIdx.z * (NCHUNK * KCH);

    const __nv_bfloat16 *Ahi = MODE ? g_hhi : g_zhi;
    const __nv_bfloat16 *Alo = MODE ? g_hlo : g_zlo;
    const __nv_bfloat16 *Bhi = MODE ? g_W2hi : g_W1hi;
    const __nv_bfloat16 *Blo = MODE ? g_W2lo : g_W1lo;

    // ---- loader lane constants ----
    const int aRow = tid >> 1;                    // 0..127
    const int aC0 = (tid & 1) * 2;                // 0 or 2
    const uint32_t aSw0 = swz(aRow, aC0);
    const uint32_t aSw1 = swz(aRow, aC0 + 1);
    const int bRow = tid & 63;                    // 0..63
    const int bC = tid >> 6;                      // 0..3
    const uint32_t bSw = swz(bRow, bC);
    const __nv_bfloat16 *pAh = Ahi + (size_t)(m0 + aRow) * LDA + kOff + aC0 * 8;
    const __nv_bfloat16 *pAl = Alo + (size_t)(m0 + aRow) * LDA + kOff + aC0 * 8;
    const __nv_bfloat16 *pBh = Bhi + (size_t)(n0 + bRow) * LDA + kOff + bC * 8;
    const __nv_bfloat16 *pBl = Blo + (size_t)(n0 + bRow) * LDA + kOff + bC * 8;

    // ---- ldmatrix lane offsets (per mt/np and k16 index kk) ----
    uint32_t offA[2][2], offB[2][2];
#pragma unroll
    for (int mt = 0; mt < 2; mt++) {
        const uint32_t r = wm * 32 + mt * 16 + (l & 15);
#pragma unroll
        for (int kk = 0; kk < 2; kk++)
            offA[mt][kk] = swz(r, (uint32_t)(l >> 4) + kk * 2);
    }
#pragma unroll
    for (int np = 0; np < 2; np++) {
        const uint32_t r = wn * 32 + np * 16 + ((l >> 4) << 3) + (l & 7);
#pragma unroll
        for (int kk = 0; kk < 2; kk++)
            offB[np][kk] = swz(r, (uint32_t)((l >> 3) & 1) + kk * 2);
    }

    float acc[2][4][4];
#pragma unroll
    for (int mt = 0; mt < 2; mt++)
#pragma unroll
        for (int nt = 0; nt < 4; nt++)
#pragma unroll
            for (int i = 0; i < 4; i++) acc[mt][nt][i] = 0.0f;

    auto load = [&](int c, int st) {
        const uint32_t sb = s0 + (uint32_t)st * STAGE;
        const int e = c * KCH;
        cp16(sb + aSw0, pAh + e);            cp16(sb + aSw1, pAh + e + 8);
        cp16(sb + OFF_ALO + aSw0, pAl + e);  cp16(sb + OFF_ALO + aSw1, pAl + e + 8);
        cp16(sb + OFF_BHI + bSw, pBh + e);
        cp16(sb + OFF_BLO + bSw, pBl + e);
        cp_commit();
    };

    load(0, 0);
    load(1, 1);

#pragma unroll 1
    for (int c = 0; c < NCHUNK; c++) {
        const int st = c & 1;
        if (c < NCHUNK - 1) cp_wait<1>(); else cp_wait<0>();
        __syncthreads();

        const uint32_t sb = s0 + (uint32_t)st * STAGE;
#pragma unroll
        for (int kk = 0; kk < 2; kk++) {
            uint32_t aF[2][2][4], bF[2][2][4];
#pragma unroll
            for (int mt = 0; mt < 2; mt++) {
                ldsm4(aF[0][mt][0], aF[0][mt][1], aF[0][mt][2], aF[0][mt][3],
                      sb + offA[mt][kk]);
                ldsm4(aF[1][mt][0], aF[1][mt][1], aF[1][mt][2], aF[1][mt][3],
                      sb + OFF_ALO + offA[mt][kk]);
            }
#pragma unroll
            for (int np = 0; np < 2; np++) {
                ldsm4(bF[0][np][0], bF[0][np][1], bF[0][np][2], bF[0][np][3],
                      sb + OFF_BHI + offB[np][kk]);
                ldsm4(bF[1][np][0], bF[1][np][1], bF[1][np][2], bF[1][np][3],
                      sb + OFF_BLO + offB[np][kk]);
            }
#pragma unroll
            for (int mt = 0; mt < 2; mt++)
#pragma unroll
                for (int nt = 0; nt < 4; nt++) {
                    const uint32_t *bh = &bF[0][nt >> 1][(nt & 1) * 2];
                    const uint32_t *bl = &bF[1][nt >> 1][(nt & 1) * 2];
                    mma16816(acc[mt][nt], aF[0][mt], bh);   // hi*hi
                    mma16816(acc[mt][nt], aF[0][mt], bl);   // hi*lo
                    mma16816(acc[mt][nt], aF[1][mt], bh);   // lo*hi
                }
        }

        if (c + 2 < NCHUNK) {
            __syncthreads();
            load(c + 2, st);
        }
    }

    // ---- epilogue: raw fp32 partials ----
    const int LDO = MODE ? ZD : HD;
    float *dst = (MODE ? g_dzp[blockIdx.z] : g_hp[blockIdx.z]);
#pragma unroll
    for (int mt = 0; mt < 2; mt++) {
        const int mr = m0 + wm * 32 + mt * 16 + g;
#pragma unroll
        for (int nt = 0; nt < 4; nt++) {
            const int n = n0 + wn * 32 + nt * 8 + tig * 2;
            *(float2 *)(dst + (size_t)mr * LDO + n) =
                make_float2(acc[mt][nt][0], acc[mt][nt][1]);
            *(float2 *)(dst + (size_t)(mr + 8) * LDO + n) =
                make_float2(acc[mt][nt][2], acc[mt][nt][3]);
        }
    }
}

// ---------------- reduce + tanh + split for h ------------------------------
__global__ void __launch_bounds__(256)
hsplit_kernel(const float *__restrict__ wt, const float *__restrict__ b1,
              const float *__restrict__ ts, int step) {
    const int base = (blockIdx.x * 256 + threadIdx.x) * 4;  // < NB*HD
    const float t = ts[step];
    const int n = base & (HD - 1);
    const float4 p0 = *(const float4 *)(g_hp[0] + base);
    const float4 p1 = *(const float4 *)(g_hp[1] + base);
    const float4 w = *(const float4 *)(wt + n);
    const float4 b = *(const float4 *)(b1 + n);
    const float v0 = tanhf(p0.x + p1.x + fmaf(t, w.x, b.x));
    const float v1 = tanhf(p0.y + p1.y + fmaf(t, w.y, b.y));
    const float v2 = tanhf(p0.z + p1.z + fmaf(t, w.z, b.z));
    const float v3 = tanhf(p0.w + p1.w + fmaf(t, w.w, b.w));
    __nv_bfloat16 h[4], l[4];
    bf16_split(v0, h[0], l[0]); bf16_split(v1, h[1], l[1]);
    bf16_split(v2, h[2], l[2]); bf16_split(v3, h[3], l[3]);
    *(uint2 *)(g_hhi + base) = make_uint2(pack2(h[0], h[1]), pack2(h[2], h[3]));
    *(uint2 *)(g_hlo + base) = make_uint2(pack2(l[0], l[1]), pack2(l[2], l[3]));
}

// ---------------- Euler update (4 partials) --------------------------------
__global__ void __launch_bounds__(256)
euler_kernel(const float *__restrict__ b2, const float *__restrict__ ts, int step) {
    const int base = (blockIdx.x * 256 + threadIdx.x) * 4;  // < NP
    const float dt = ts[step + 1] - ts[step];
    const float4 a0 = *(const float4 *)(g_dzp[0] + base);
    const float4 a1 = *(const float4 *)(g_dzp[1] + base);
    const float4 a2 = *(const float4 *)(g_dzp[2] + base);
    const float4 a3 = *(const float4 *)(g_dzp[3] + base);
    const float4 z = *(const float4 *)(g_z + base);
    const int n = base & (ZD - 1);
    const float4 bb = *(const float4 *)(b2 + n);
    float4 zn;
    zn.x = fmaf(dt, (a0.x + a1.x) + (a2.x + a3.x) + bb.x, z.x);
    zn.y = fmaf(dt, (a0.y + a1.y) + (a2.y + a3.y) + bb.y, z.y);
    zn.z = fmaf(dt, (a0.z + a1.z) + (a2.z + a3.z) + bb.z, z.z);
    zn.w = fmaf(dt, (a0.w + a1.w) + (a2.w + a3.w) + bb.w, z.w);
    *(float4 *)(g_z + base) = zn;
    *(float4 *)(g_traj + (size_t)(step + 1) * NP + base) = zn;
    __nv_bfloat16 h[4], l[4];
    bf16_split(zn.x, h[0], l[0]); bf16_split(zn.y, h[1], l[1]);
    bf16_split(zn.z, h[2], l[2]); bf16_split(zn.w, h[3], l[3]);
    *(uint2 *)(g_zhi + base) = make_uint2(pack2(h[0], h[1]), pack2(h[2], h[3]));
    *(uint2 *)(g_zlo + base) = make_uint2(pack2(l[0], l[1]), pack2(l[2], l[3]));
}

__global__ void __launch_bounds__(256)
init_kernel(const float *__restrict__ z0) {
    const int base = (blockIdx.x * 256 + threadIdx.x) * 4;
    const float4 v = *(const float4 *)(z0 + base);
    *(float4 *)(g_z + base) = v;
    *(float4 *)(g_traj + base) = v;
    __nv_bfloat16 h[4], l[4];
    bf16_split(v.x, h[0], l[0]); bf16_split(v.y, h[1], l[1]);
    bf16_split(v.z, h[2], l[2]); bf16_split(v.w, h[3], l[3]);
    *(uint2 *)(g_zhi + base) = make_uint2(pack2(h[0], h[1]), pack2(h[2], h[3]));
    *(uint2 *)(g_zlo + base) = make_uint2(pack2(l[0], l[1]), pack2(l[2], l[3]));
}

__global__ void __launch_bounds__(256)
wsplit_kernel(const float *__restrict__ src, int which) {
    const int base = (blockIdx.x * 256 + threadIdx.x) * 4;
    __nv_bfloat16 *dh = which ? g_W2hi : g_W1hi;
    __nv_bfloat16 *dl = which ? g_W2lo : g_W1lo;
    const float4 v = *(const float4 *)(src + base);
    __nv_bfloat16 h[4], l[4];
    bf16_split(v.x, h[0], l[0]); bf16_split(v.y, h[1], l[1]);
    bf16_split(v.z, h[2], l[2]); bf16_split(v.w, h[3], l[3]);
    *(uint2 *)(dh + base) = make_uint2(pack2(h[0], h[1]), pack2(h[2], h[3]));
    *(uint2 *)(dl + base) = make_uint2(pack2(l[0], l[1]), pack2(l[2], l[3]));
}

// [T][B*Z] -> [B*Z][T]
__global__ void __launch_bounds__(256)
transpose_kernel(float *__restrict__ out) {
    __shared__ float sm[32][33];
    const int p0 = blockIdx.x * 32;
    const int t0 = blockIdx.y * 32;
    const int tx = threadIdx.x;
    const int ty = threadIdx.y;
#pragma unroll
    for (int i = 0; i < 4; i++) {
        const int tl = ty + 8 * i;
        sm[tl][tx] = g_traj[(size_t)(t0 + tl) * NP + p0 + tx];
    }
    __syncthreads();
#pragma unroll
    for (int i = 0; i < 4; i++) {
        const int pl = ty + 8 * i;
        out[(size_t)(p0 + pl) * NT + t0 + tx] = sm[tx][pl];
    }
}

// ---------------------------------------------------------------------------
extern "C" void kernel_launch(void *const *d_in, const int *in_sizes, int n_in,
                              void *d_out, int out_size) {
    const float *z0 = (const float *)d_in[0];
    const float *ts = (const float *)d_in[1];
    const float *W1 = (const float *)d_in[2];
    const float *wt = (const float *)d_in[3];
    const float *b1 = (const float *)d_in[4];
    const float *W2 = (const float *)d_in[5];
    const float *b2 = (const float *)d_in[6];
    float *out = (float *)d_out;

    wsplit_kernel<<<(HD * ZD) / 1024, 256>>>(W1, 0);
    wsplit_kernel<<<(HD * ZD) / 1024, 256>>>(W2, 1);
    init_kernel<<<NP / 1024, 256>>>(z0);

    for (int s = 0; s < NT - 1; ++s) {
        // partials of z @ W1^T (split-K=2): 128 CTAs x 256 thr
        gemm_mma<ZD, 0><<<dim3(HD / 64, NB / 128, 2), 256>>>();
        // h = tanh(sum + t*wt + b1) -> bf16 splits
        hsplit_kernel<<<(NB * HD) / 1024, 256>>>(wt, b1, ts, s);
        // partials of h @ W2^T (split-K=4): 128 CTAs x 256 thr
        gemm_mma<HD, 1><<<dim3(ZD / 64, NB / 128, 4), 256>>>();
        // z += dt*(dz + b2); trajectory slice s+1
        euler_kernel<<<NP / 1024, 256>>>(b2, ts, s);
    }

    transpose_kernel<<<dim3(NP / 32, NT / 32), dim3(32, 8)>>>(out);
}

// round 9
// speedup vs baseline: 3.5850x; 1.2262x over previous
#include <cuda_runtime.h>
#include <cuda_bf16.h>
#include <math.h>
#include <stdint.h>

#define NB 256
#define ZD 1024
#define HD 2048
#define NT 128
#define NP (NB * ZD)

#define KCH 16            // k elements per chunk
#define NCHUNK 16         // K slab = 256 per CTA
#define SPLIT1 4          // GEMM1 split-K (1024/256)
#define SPLIT2 8          // GEMM2 split-K (2048/256)
#define OFF_ALO 4096      // region offsets inside a stage
#define OFF_BHI 8192
#define OFF_BLO 10240
#define STAGE 12288       // Ahi 4K + Alo 4K + Bhi 2K + Blo 2K
#define STAGES 3          // 36864 B static smem -> 2 CTAs/SM

// ---------------- device scratch ------------------------------------------
__device__ float g_hp[SPLIT1][NB * HD];   // GEMM1 split-K partials
__device__ float g_dzp[SPLIT2][NB * ZD];  // GEMM2 split-K partials
__device__ float g_z[NP];
__device__ float g_traj[NT * NP];
__device__ __nv_bfloat16 g_zhi[NP], g_zlo[NP];
__device__ __nv_bfloat16 g_hhi[NB * HD], g_hlo[NB * HD];
__device__ __nv_bfloat16 g_W1hi[HD * ZD], g_W1lo[HD * ZD];
__device__ __nv_bfloat16 g_W2hi[ZD * HD], g_W2lo[ZD * HD];

// ---------------- PTX helpers ---------------------------------------------
__device__ __forceinline__ void cp16(uint32_t dst, const void *src) {
    asm volatile("cp.async.cg.shared.global [%0], [%1], 16;" :: "r"(dst), "l"(src));
}
__device__ __forceinline__ void cp_commit() {
    asm volatile("cp.async.commit_group;" ::: "memory");
}
template <int N>
__device__ __forceinline__ void cp_wait() {
    asm volatile("cp.async.wait_group %0;" :: "n"(N) : "memory");
}
__device__ __forceinline__ void ldsm4(uint32_t &r0, uint32_t &r1, uint32_t &r2,
                                      uint32_t &r3, uint32_t a) {
    asm volatile("ldmatrix.sync.aligned.m8n8.x4.shared.b16 {%0,%1,%2,%3}, [%4];"
                 : "=r"(r0), "=r"(r1), "=r"(r2), "=r"(r3) : "r"(a));
}
__device__ __forceinline__ void mma16816(float *c, const uint32_t *a,
                                         const uint32_t *b) {
    asm volatile(
        "mma.sync.aligned.m16n8k16.row.col.f32.bf16.bf16.f32 "
        "{%0,%1,%2,%3}, {%4,%5,%6,%7}, {%8,%9}, {%0,%1,%2,%3};"
        : "+f"(c[0]), "+f"(c[1]), "+f"(c[2]), "+f"(c[3])
        : "r"(a[0]), "r"(a[1]), "r"(a[2]), "r"(a[3]), "r"(b[0]), "r"(b[1]));
}
__device__ __forceinline__ void bf16_split(float v, __nv_bfloat16 &hi,
                                           __nv_bfloat16 &lo) {
    hi = __float2bfloat16_rn(v);
    lo = __float2bfloat16_rn(v - __bfloat162float(hi));
}
__device__ __forceinline__ uint32_t pack2(__nv_bfloat16 a, __nv_bfloat16 b) {
    return (uint32_t)__bfloat16_as_ushort(a) |
           ((uint32_t)__bfloat16_as_ushort(b) << 16);
}
// swizzled byte offset inside one region (row r, 16B-column c16 in {0,1})
__device__ __forceinline__ uint32_t swz(uint32_t r, uint32_t c16) {
    return r * 32u + ((c16 ^ ((r >> 2) & 1u)) << 4);
}

// ---------------- warp-MMA GEMM (128m x 64n CTA tile, 256 thr, split-K) ----
// D[m,n] = sum_k A[m,k]*B[n,k] via 3 bf16 products (hi*hi + hi*lo + lo*hi).
// MODE 0: A = z splits (LDA=1024), B = W1 splits; out -> g_hp[z]
// MODE 1: A = h splits (LDA=2048), B = W2 splits; out -> g_dzp[z]
template <int LDA, int MODE>
__global__ void __launch_bounds__(256)
gemm_mma() {
    __shared__ __align__(128) char smem[STAGES * STAGE];
    const uint32_t s0 = (uint32_t)__cvta_generic_to_shared(smem);

    const int tid = threadIdx.x;
    const int wid = tid >> 5, l = tid & 31;
    const int wm = wid & 3, wn = wid >> 2;        // warp grid 4(m) x 2(n)
    const int g = l >> 2, tig = l & 3;

    const int m0 = blockIdx.y * 128, n0 = blockIdx.x * 64;
    const int kOff = (int)blockIdx.z * (NCHUNK * KCH);

    const __nv_bfloat16 *Ahi = MODE ? g_hhi : g_zhi;
    const __nv_bfloat16 *Alo = MODE ? g_hlo : g_zlo;
    const __nv_bfloat16 *Bhi = MODE ? g_W2hi : g_W1hi;
    const __nv_bfloat16 *Blo = MODE ? g_W2lo : g_W1lo;

    // ---- loader lane constants ----
    // A: 128 rows x 2 halves (16B) per split; every thread does hi+lo.
    const int aRow = tid >> 1;                    // 0..127
    const int aC = tid & 1;                       // 16B half
    const uint32_t aSw = swz(aRow, aC);
    const __nv_bfloat16 *pAh = Ahi + (size_t)(m0 + aRow) * LDA + kOff + aC * 8;
    const __nv_bfloat16 *pAl = Alo + (size_t)(m0 + aRow) * LDA + kOff + aC * 8;
    // B: 64 rows x 2 halves per split; threads 0-127 -> hi, 128-255 -> lo.
    const int bRow = (tid & 127) >> 1;
    const int bC = tid & 1;
    const int bLo = tid >> 7;                     // 0: hi, 1: lo
    const uint32_t bSw = (uint32_t)(OFF_BHI + bLo * 2048) + swz(bRow, bC);
    const __nv_bfloat16 *pB =
        (bLo ? Blo : Bhi) + (size_t)(n0 + bRow) * LDA + kOff + bC * 8;

    // ---- ldmatrix lane offsets ----
    uint32_t offA[2], offB[2];
#pragma unroll
    for (int mt = 0; mt < 2; mt++)
        offA[mt] = swz((uint32_t)(wm * 32 + mt * 16 + (l & 15)), (uint32_t)(l >> 4));
#pragma unroll
    for (int np = 0; np < 2; np++)
        offB[np] = swz((uint32_t)(wn * 32 + np * 16 + ((l >> 4) << 3) + (l & 7)),
                       (uint32_t)((l >> 3) & 1));

    float acc[2][4][4];
#pragma unroll
    for (int mt = 0; mt < 2; mt++)
#pragma unroll
        for (int nt = 0; nt < 4; nt++)
#pragma unroll
            for (int i = 0; i < 4; i++) acc[mt][nt][i] = 0.0f;

    auto load = [&](int c, int st) {
        const uint32_t sb = s0 + (uint32_t)st * STAGE;
        const int e = c * KCH;
        cp16(sb + aSw, pAh + e);
        cp16(sb + OFF_ALO + aSw, pAl + e);
        cp16(sb + bSw, pB + e);
        cp_commit();
    };

    load(0, 0);
    load(1, 1);

#pragma unroll 1
    for (int c = 0; c < NCHUNK; c++) {
        const int st = c % 3;
        if (c < NCHUNK - 1) cp_wait<1>(); else cp_wait<0>();
        __syncthreads();                       // one barrier per chunk (S=3)
        if (c + 2 < NCHUNK) load(c + 2, (c + 2) % 3);

        const uint32_t sb = s0 + (uint32_t)st * STAGE;
        uint32_t aF[2][2][4], bF[2][2][4];
#pragma unroll
        for (int mt = 0; mt < 2; mt++) {
            ldsm4(aF[0][mt][0], aF[0][mt][1], aF[0][mt][2], aF[0][mt][3],
                  sb + offA[mt]);
            ldsm4(aF[1][mt][0], aF[1][mt][1], aF[1][mt][2], aF[1][mt][3],
                  sb + OFF_ALO + offA[mt]);
        }
#pragma unroll
        for (int np = 0; np < 2; np++) {
            ldsm4(bF[0][np][0], bF[0][np][1], bF[0][np][2], bF[0][np][3],
                  sb + OFF_BHI + offB[np]);
            ldsm4(bF[1][np][0], bF[1][np][1], bF[1][np][2], bF[1][np][3],
                  sb + OFF_BLO + offB[np]);
        }
#pragma unroll
        for (int mt = 0; mt < 2; mt++)
#pragma unroll
            for (int nt = 0; nt < 4; nt++) {
                const uint32_t *bh = &bF[0][nt >> 1][(nt & 1) * 2];
                const uint32_t *bl = &bF[1][nt >> 1][(nt & 1) * 2];
                mma16816(acc[mt][nt], aF[0][mt], bh);   // hi*hi
                mma16816(acc[mt][nt], aF[0][mt], bl);   // hi*lo
                mma16816(acc[mt][nt], aF[1][mt], bh);   // lo*hi
            }
    }

    // ---- epilogue: raw fp32 partials ----
    const int LDO = MODE ? ZD : HD;
    float *dst = (MODE ? g_dzp[blockIdx.z] : g_hp[blockIdx.z]);
#pragma unroll
    for (int mt = 0; mt < 2; mt++) {
        const int mr = m0 + wm * 32 + mt * 16 + g;
#pragma unroll
        for (int nt = 0; nt < 4; nt++) {
            const int n = n0 + wn * 32 + nt * 8 + tig * 2;
            *(float2 *)(dst + (size_t)mr * LDO + n) =
                make_float2(acc[mt][nt][0], acc[mt][nt][1]);
            *(float2 *)(dst + (size_t)(mr + 8) * LDO + n) =
                make_float2(acc[mt][nt][2], acc[mt][nt][3]);
        }
    }
}

// ---------------- reduce + tanh + split for h ------------------------------
__global__ void __launch_bounds__(256)
hsplit_kernel(const float *__restrict__ wt, const float *__restrict__ b1,
              const float *__restrict__ ts, int step) {
    const int base = (blockIdx.x * 256 + threadIdx.x) * 4;  // < NB*HD
    const float t = ts[step];
    const int n = base & (HD - 1);
    float4 s = *(const float4 *)(g_hp[0] + base);
#pragma unroll
    for (int p = 1; p < SPLIT1; p++) {
        const float4 q = *(const float4 *)(g_hp[p] + base);
        s.x += q.x; s.y += q.y; s.z += q.z; s.w += q.w;
    }
    const float4 w = *(const float4 *)(wt + n);
    const float4 b = *(const float4 *)(b1 + n);
    const float v0 = tanhf(s.x + fmaf(t, w.x, b.x));
    const float v1 = tanhf(s.y + fmaf(t, w.y, b.y));
    const float v2 = tanhf(s.z + fmaf(t, w.z, b.z));
    const float v3 = tanhf(s.w + fmaf(t, w.w, b.w));
    __nv_bfloat16 h[4], l[4];
    bf16_split(v0, h[0], l[0]); bf16_split(v1, h[1], l[1]);
    bf16_split(v2, h[2], l[2]); bf16_split(v3, h[3], l[3]);
    *(uint2 *)(g_hhi + base) = make_uint2(pack2(h[0], h[1]), pack2(h[2], h[3]));
    *(uint2 *)(g_hlo + base) = make_uint2(pack2(l[0], l[1]), pack2(l[2], l[3]));
}

// ---------------- Euler update (SPLIT2 partials) ---------------------------
__global__ void __launch_bounds__(256)
euler_kernel(const float *__restrict__ b2, const float *__restrict__ ts, int step) {
    const int base = (blockIdx.x * 256 + threadIdx.x) * 4;  // < NP
    const float dt = ts[step + 1] - ts[step];
    float4 s = *(const float4 *)(g_dzp[0] + base);
#pragma unroll
    for (int p = 1; p < SPLIT2; p++) {
        const float4 q = *(const float4 *)(g_dzp[p] + base);
        s.x += q.x; s.y += q.y; s.z += q.z; s.w += q.w;
    }
    const float4 z = *(const float4 *)(g_z + base);
    const int n = base & (ZD - 1);
    const float4 bb = *(const float4 *)(b2 + n);
    float4 zn;
    zn.x = fmaf(dt, s.x + bb.x, z.x);
    zn.y = fmaf(dt, s.y + bb.y, z.y);
    zn.z = fmaf(dt, s.z + bb.z, z.z);
    zn.w = fmaf(dt, s.w + bb.w, z.w);
    *(float4 *)(g_z + base) = zn;
    *(float4 *)(g_traj + (size_t)(step + 1) * NP + base) = zn;
    __nv_bfloat16 h[4], l[4];
    bf16_split(zn.x, h[0], l[0]); bf16_split(zn.y, h[1], l[1]);
    bf16_split(zn.z, h[2], l[2]); bf16_split(zn.w, h[3], l[3]);
    *(uint2 *)(g_zhi + base) = make_uint2(pack2(h[0], h[1]), pack2(h[2], h[3]));
    *(uint2 *)(g_zlo + base) = make_uint2(pack2(l[0], l[1]), pack2(l[2], l[3]));
}

__global__ void __launch_bounds__(256)
init_kernel(const float *__restrict__ z0) {
    const int base = (blockIdx.x * 256 + threadIdx.x) * 4;
    const float4 v = *(const float4 *)(z0 + base);
    *(float4 *)(g_z + base) = v;
    *(float4 *)(g_traj + base) = v;
    __nv_bfloat16 h[4], l[4];
    bf16_split(v.x, h[0], l[0]); bf16_split(v.y, h[1], l[1]);
    bf16_split(v.z, h[2], l[2]); bf16_split(v.w, h[3], l[3]);
    *(uint2 *)(g_zhi + base) = make_uint2(pack2(h[0], h[1]), pack2(h[2], h[3]));
    *(uint2 *)(g_zlo + base) = make_uint2(pack2(l[0], l[1]), pack2(l[2], l[3]));
}

__global__ void __launch_bounds__(256)
wsplit_kernel(const float *__restrict__ src, int which) {
    const int base = (blockIdx.x * 256 + threadIdx.x) * 4;
    __nv_bfloat16 *dh = which ? g_W2hi : g_W1hi;
    __nv_bfloat16 *dl = which ? g_W2lo : g_W1lo;
    const float4 v = *(const float4 *)(src + base);
    __nv_bfloat16 h[4], l[4];
    bf16_split(v.x, h[0], l[0]); bf16_split(v.y, h[1], l[1]);
    bf16_split(v.z, h[2], l[2]); bf16_split(v.w, h[3], l[3]);
    *(uint2 *)(dh + base) = make_uint2(pack2(h[0], h[1]), pack2(h[2], h[3]));
    *(uint2 *)(dl + base) = make_uint2(pack2(l[0], l[1]), pack2(l[2], l[3]));
}

// [T][B*Z] -> [B*Z][T]
__global__ void __launch_bounds__(256)
transpose_kernel(float *__restrict__ out) {
    __shared__ float sm[32][33];
    const int p0 = blockIdx.x * 32;
    const int t0 = blockIdx.y * 32;
    const int tx = threadIdx.x;
    const int ty = threadIdx.y;
#pragma unroll
    for (int i = 0; i < 4; i++) {
        const int tl = ty + 8 * i;
        sm[tl][tx] = g_traj[(size_t)(t0 + tl) * NP + p0 + tx];
    }
    __syncthreads();
#pragma unroll
    for (int i = 0; i < 4; i++) {
        const int pl = ty + 8 * i;
        out[(size_t)(p0 + pl) * NT + t0 + tx] = sm[tx][pl];
    }
}

// ---------------------------------------------------------------------------
extern "C" void kernel_launch(void *const *d_in, const int *in_sizes, int n_in,
                              void *d_out, int out_size) {
    const float *z0 = (const float *)d_in[0];
    const float *ts = (const float *)d_in[1];
    const float *W1 = (const float *)d_in[2];
    const float *wt = (const float *)d_in[3];
    const float *b1 = (const float *)d_in[4];
    const float *W2 = (const float *)d_in[5];
    const float *b2 = (const float *)d_in[6];
    float *out = (float *)d_out;

    wsplit_kernel<<<(HD * ZD) / 1024, 256>>>(W1, 0);
    wsplit_kernel<<<(HD * ZD) / 1024, 256>>>(W2, 1);
    init_kernel<<<NP / 1024, 256>>>(z0);

    for (int s = 0; s < NT - 1; ++s) {
        // partials of z @ W1^T (split-K=4): 256 CTAs x 256 thr
        gemm_mma<ZD, 0><<<dim3(HD / 64, NB / 128, SPLIT1), 256>>>();
        // h = tanh(sum + t*wt + b1) -> bf16 splits
        hsplit_kernel<<<(NB * HD) / 1024, 256>>>(wt, b1, ts, s);
        // partials of h @ W2^T (split-K=8): 256 CTAs x 256 thr
        gemm_mma<HD, 1><<<dim3(ZD / 64, NB / 128, SPLIT2), 256>>>();
        // z += dt*(dz + b2); trajectory slice s+1
        euler_kernel<<<NP / 1024, 256>>>(b2, ts, s);
    }

    transpose_kernel<<<dim3(NP / 32, NT / 32), dim3(32, 8)>>>(out);
}